// round 8
// baseline (speedup 1.0000x reference)
#include <cuda_runtime.h>
#include <cuda_bf16.h>
#include <mma.h>
#include <math.h>
#include <stdint.h>

using namespace nvcuda;

#define T_STEPS 1024
#define BATCH   256
#define E_DIM   128

__device__ float g_xproj[134217728];
__device__ float g_hx[2][32][4][256];      // h exchange: [parity][group][gc][e2*8+b]
__device__ unsigned int g_flag[32];        // monotonic per-group step counters

// ---------------------------------------------------------------------------
// Kernel 1: x_proj = x @ W_ih^T + bias, tf32 wmma + cp.async double buffering.
// ---------------------------------------------------------------------------
__device__ __forceinline__ uint32_t smem_u32(const void* p) {
    uint32_t a;
    asm("{ .reg .u64 t; cvta.to.shared.u64 t, %1; cvt.u32.u64 %0, t; }" : "=r"(a) : "l"(p));
    return a;
}
__device__ __forceinline__ void cp16(uint32_t dst, const void* src) {
    asm volatile("cp.async.cg.shared.global [%0], [%1], 16;" :: "r"(dst), "l"(src));
}
__device__ __forceinline__ void cp_commit() { asm volatile("cp.async.commit_group;"); }
__device__ __forceinline__ void cp_wait0()  { asm volatile("cp.async.wait_group 0;"); }

#define GP 36   // smem pitch (floats)

__global__ __launch_bounds__(256, 2)
void xproj_gemm_pipe(const float* __restrict__ A,
                     const float* __restrict__ W,
                     const float* __restrict__ bih,
                     const float* __restrict__ bhh)
{
    extern __shared__ float sm[];
    // layout: As[2][128*GP], Bs[2][128*GP], BiasT[16*132]
    float* Bsm   = sm + 2 * 128 * GP;
    float* BiasT = sm + 4 * 128 * GP;

    const int n0  = blockIdx.x * 128;
    const int m0  = blockIdx.y * 128;
    const int tid = threadIdx.x;
    const int warp = tid >> 5;
    const int wm = (warp >> 2) * 64;
    const int wn = (warp & 3) * 32;

    const uint32_t as_b = smem_u32(sm);
    const uint32_t bs_b = smem_u32(Bsm);
    const int lrow = tid >> 3;           // 0..31 per 256-chunk -> full via 4 iters
    const int lkq  = (tid & 7) * 4;

    for (int i = tid; i < 16 * 128; i += 256) {
        int r = i >> 7, c = i & 127;
        BiasT[r * 132 + c] = bih[n0 + c] + bhh[n0 + c];
    }
    __syncthreads();

    wmma::fragment<wmma::accumulator, 16, 16, 8, float> cf[4][2];
#pragma unroll
    for (int i = 0; i < 4; i++)
#pragma unroll
        for (int j = 0; j < 2; j++)
            wmma::load_matrix_sync(cf[i][j], &BiasT[wn + j * 16], 132, wmma::mem_row_major);
    __syncthreads();

    // issue loads for k-tile kt into stage s
    auto issue = [&](int kt, int s) {
#pragma unroll
        for (int ld = 0; ld < 4; ld++) {
            int row = lrow + ld * 32;
            cp16(as_b + (uint32_t)(s * 128 * GP + row * GP + lkq) * 4,
                 &A[(size_t)(m0 + row) * 256 + kt * 32 + lkq]);
            cp16(bs_b + (uint32_t)(s * 128 * GP + row * GP + lkq) * 4,
                 &W[(size_t)(n0 + row) * 256 + kt * 32 + lkq]);
        }
        cp_commit();
    };

    issue(0, 0);
    for (int kt = 0; kt < 8; kt++) {
        int s = kt & 1;
        cp_wait0();
        __syncthreads();
        if (kt < 7) issue(kt + 1, s ^ 1);
        const float* As = sm + s * 128 * GP;
        const float* Bs = Bsm + s * 128 * GP;
#pragma unroll
        for (int kk = 0; kk < 32; kk += 8) {
            wmma::fragment<wmma::matrix_a, 16, 16, 8, wmma::precision::tf32, wmma::row_major> af[4];
            wmma::fragment<wmma::matrix_b, 16, 16, 8, wmma::precision::tf32, wmma::col_major> bf[2];
#pragma unroll
            for (int i = 0; i < 4; i++) {
                wmma::load_matrix_sync(af[i], &As[(wm + i * 16) * GP + kk], GP);
#pragma unroll
                for (int t = 0; t < af[i].num_elements; t++)
                    af[i].x[t] = wmma::__float_to_tf32(af[i].x[t]);
            }
#pragma unroll
            for (int j = 0; j < 2; j++) {
                wmma::load_matrix_sync(bf[j], &Bs[(wn + j * 16) * GP + kk], GP);
#pragma unroll
                for (int t = 0; t < bf[j].num_elements; t++)
                    bf[j].x[t] = wmma::__float_to_tf32(bf[j].x[t]);
            }
#pragma unroll
            for (int i = 0; i < 4; i++)
#pragma unroll
                for (int j = 0; j < 2; j++)
                    wmma::mma_sync(cf[i][j], af[i], bf[j], cf[i][j]);
        }
    }
#pragma unroll
    for (int i = 0; i < 4; i++)
#pragma unroll
        for (int j = 0; j < 2; j++)
            wmma::store_matrix_sync(
                &g_xproj[(size_t)(m0 + wm + i * 16) * 512 + n0 + wn + j * 16],
                cf[i][j], 512, wmma::mem_row_major);
}
#define GEMM_SMEM ((4 * 128 * GP + 16 * 132) * 4)

// ---------------------------------------------------------------------------
// Recurrence helpers (validated in R7)
// ---------------------------------------------------------------------------
__device__ __forceinline__ void mma16816(float* c, const uint32_t* a, uint32_t b0, uint32_t b1) {
    asm volatile(
        "mma.sync.aligned.m16n8k16.row.col.f32.bf16.bf16.f32 "
        "{%0,%1,%2,%3}, {%4,%5,%6,%7}, {%8,%9}, {%0,%1,%2,%3};"
        : "+f"(c[0]), "+f"(c[1]), "+f"(c[2]), "+f"(c[3])
        : "r"(a[0]), "r"(a[1]), "r"(a[2]), "r"(a[3]), "r"(b0), "r"(b1));
}
__device__ __forceinline__ void ldmx4(uint32_t& r0, uint32_t& r1, uint32_t& r2, uint32_t& r3,
                                      uint32_t addr) {
    asm volatile("ldmatrix.sync.aligned.m8n8.x4.shared.b16 {%0,%1,%2,%3}, [%4];"
                 : "=r"(r0), "=r"(r1), "=r"(r2), "=r"(r3) : "r"(addr));
}
__device__ __forceinline__ unsigned short bfh(float v) { return __bfloat16_as_ushort(__float2bfloat16(v)); }
__device__ __forceinline__ float bfv(unsigned short u) { return __bfloat162float(__ushort_as_bfloat16(u)); }
__device__ __forceinline__ uint32_t pkbf(float2 f) {
    return ((uint32_t)bfh(f.y) << 16) | (uint32_t)bfh(f.x);
}
__device__ __forceinline__ float sigm(float x)   { return __fdividef(1.f, 1.f + __expf(-x)); }
__device__ __forceinline__ float tanhf_(float x) { float e = __expf(2.f * x); return 1.f - __fdividef(2.f, e + 1.f); }
__device__ __forceinline__ unsigned ld_acq(const unsigned* p) {
    unsigned v;
    asm volatile("ld.acquire.gpu.global.u32 %0, [%1];" : "=r"(v) : "l"(p) : "memory");
    return v;
}

// smem layout (bytes): W_lo 32KB | BHI 2KB | BLO 2KB | gates 4KB
#define WLO_OFF  0
#define BHI_OFF  32768
#define BLO_OFF  34816
#define GSM_OFF  36864
#define REC_SMEM 40960

__device__ __forceinline__ void write_h(char* smem, int e, int b, float h) {
    unsigned short hh = bfh(h);
    unsigned short hl = bfh(h - bfv(hh));
    int kt = e >> 4, kk = e & 15;
    int half = kk >> 3, tq = (kk & 7) >> 1, lo = kk & 1;
    uint32_t byte = (uint32_t)(kt * 64 + (b * 4 + tq) * 2 + half) * 4 + lo * 2;
    *reinterpret_cast<unsigned short*>(smem + BHI_OFF + byte) = hh;
    *reinterpret_cast<unsigned short*>(smem + BLO_OFF + byte) = hl;
}

// ---------------------------------------------------------------------------
// Kernel 2: LSTM recurrence, 128 CTAs = 32 groups x 4 e-slices.
// CTA (group, gc): computes gate rows {128q + 32gc + j, q=0..3, j=0..31} for
// 8 batches. Epilogue fully CTA-local for its e-slice; h exchanged through L2
// with release/acquire flags. 3 MMA terms: Whi@hhi + Whi@hlo + Wlo@hhi.
// ---------------------------------------------------------------------------
__global__ __launch_bounds__(256, 1)
void lstm_rec_x(const float* __restrict__ Whh,
                const float* __restrict__ h0,
                const float* __restrict__ c0,
                float* __restrict__ out)
{
    extern __shared__ char smem[];
    float* gsm = reinterpret_cast<float*>(smem + GSM_OFF);  // [4][32][8]
    const int tid = threadIdx.x;
    const int w   = tid >> 5;
    const int l   = tid & 31;
    const int group = blockIdx.x >> 2;
    const int gc    = blockIdx.x & 3;
    const int bg0   = group * 8;
    const int q     = w >> 1;           // gate type of this warp

    // ---- W_lo -> smem: 128 rows (this CTA's row set), quad-blocked tiles ----
    for (int idx = tid; idx < 128 * 32; idx += 256) {
        int i  = idx >> 5;                       // local tile row 0..127
        int kq = (idx & 31) * 4;
        int G  = 128 * (i >> 5) + 32 * gc + (i & 31);   // global gate row
        float4 v = *reinterpret_cast<const float4*>(&Whh[(size_t)G * 128 + kq]);
        float vv[4] = {v.x, v.y, v.z, v.w};
#pragma unroll
        for (int j = 0; j < 4; j++) {
            int k = kq + j;
            float lo = vv[j] - bfv(bfh(vv[j]));
            uint32_t byte = (uint32_t)((i >> 4) * 4096 + (k >> 4) * 512
                          + (((i >> 3) & 1) + 2 * ((k >> 3) & 1)) * 128
                          + (i & 7) * 16 + (k & 7) * 2);
            *reinterpret_cast<unsigned short*>(smem + WLO_OFF + byte) = bfh(lo);
        }
    }

    // ---- W_hi A-fragments: warp w owns rows 128q + 32gc + 16(w&1) + {0..15} ----
    uint32_t ahi[8][4];
    {
        const int g8 = l >> 2, t2 = (l & 3) * 2;
        const int r0 = 128 * q + 32 * gc + 16 * (w & 1) + g8;
#pragma unroll
        for (int kt = 0; kt < 8; kt++) {
            int k0 = kt * 16 + t2;
            ahi[kt][0] = pkbf(*reinterpret_cast<const float2*>(&Whh[(size_t)r0 * 128 + k0]));
            ahi[kt][1] = pkbf(*reinterpret_cast<const float2*>(&Whh[(size_t)(r0 + 8) * 128 + k0]));
            ahi[kt][2] = pkbf(*reinterpret_cast<const float2*>(&Whh[(size_t)r0 * 128 + k0 + 8]));
            ahi[kt][3] = pkbf(*reinterpret_cast<const float2*>(&Whh[(size_t)(r0 + 8) * 128 + k0 + 8]));
        }
    }

    // ---- state: thread owns one item (e2, b); e = 32gc + e2 ----
    const int e2 = tid >> 3;
    const int b  = tid & 7;
    float creg = c0[(size_t)(bg0 + b) * 128 + 32 * gc + e2];
    // init B tiles with ALL h0 (all 4 slices)
#pragma unroll
    for (int gg = 0; gg < 4; gg++) {
        float h = h0[(size_t)(bg0 + b) * 128 + 32 * gg + e2];
        write_h(smem, 32 * gg + e2, b, h);
    }

    // MMA-output coords per acc slot c: row r = 16(w&1)+(l>>2)+8(c>>1) (local
    // within 32-slice is rl = r; global row = 128q+32gc+r), batch 2(l&3)+(c&1)
    int rl[4], bm[4];
#pragma unroll
    for (int c = 0; c < 4; c++) {
        rl[c] = 16 * (w & 1) + (l >> 2) + 8 * (c >> 1);
        bm[c] = 2 * (l & 3) + (c & 1);
    }
    // xproj slot for acc slot c: g_xproj[(t*256 + bg0+bm)*512 + 128q + 32gc + rl]
    float xpc[4];
#pragma unroll
    for (int c = 0; c < 4; c++)
        xpc[c] = g_xproj[((size_t)bg0 + bm[c]) * 512 + 128 * q + 32 * gc + rl[c]];

    const uint32_t sb = smem_u32(smem);
    const uint32_t wlo_lane = sb + WLO_OFF + (uint32_t)w * 4096
                            + (uint32_t)((l >> 3) * 128 + (l & 7) * 16);
    __syncthreads();

    for (int t = 0; t < T_STEPS; t++) {
        // prefetch next step xproj
        float xpn[4];
        {
            int tn = (t + 1 < T_STEPS) ? t + 1 : t;
#pragma unroll
            for (int c = 0; c < 4; c++)
                xpn[c] = __ldg(&g_xproj[((size_t)tn * BATCH + bg0 + bm[c]) * 512
                                        + 128 * q + 32 * gc + rl[c]]);
        }

        // ---- MMA: 3 terms, 2 independent chains ----
        float accM[4] = {xpc[0], xpc[1], xpc[2], xpc[3]};
        float accC[4] = {0.f, 0.f, 0.f, 0.f};
#pragma unroll
        for (int kt = 0; kt < 8; kt++) {
            uint2 vh = *reinterpret_cast<const uint2*>(smem + BHI_OFF + kt * 256 + l * 8);
            uint2 vl = *reinterpret_cast<const uint2*>(smem + BLO_OFF + kt * 256 + l * 8);
            uint32_t qf[4];
            ldmx4(qf[0], qf[1], qf[2], qf[3], wlo_lane + kt * 512);
            mma16816(accM, ahi[kt], vh.x, vh.y);
            mma16816(accC, ahi[kt], vl.x, vl.y);
            mma16816(accC, qf, vh.x, vh.y);
        }

        // ---- gate exchange via smem: gsm[q][rl][bm] ----
        {
            float2 s0 = make_float2(accM[0] + accC[0], accM[1] + accC[1]);
            float2 s1 = make_float2(accM[2] + accC[2], accM[3] + accC[3]);
            *reinterpret_cast<float2*>(&gsm[q * 256 + rl[0] * 8 + 2 * (l & 3)]) = s0;
            *reinterpret_cast<float2*>(&gsm[q * 256 + rl[2] * 8 + 2 * (l & 3)]) = s1;
        }
        __syncthreads();

        // ---- local epilogue: one item per thread ----
        float gi = gsm[0 * 256 + tid];
        float gf = gsm[1 * 256 + tid];
        float gg_ = gsm[2 * 256 + tid];
        float go = gsm[3 * 256 + tid];
        float i_ = sigm(gi), f_ = sigm(gf), g_ = tanhf_(gg_), o_ = sigm(go);
        creg = f_ * creg + i_ * g_;
        float h = o_ * tanhf_(creg);

        const int p = t & 1;
        __stcg(&g_hx[p][group][gc][tid], h);
        out[((size_t)t * BATCH + bg0 + b) * E_DIM + 32 * gc + e2] = log1pf(__expf(h));
        write_h(smem, 32 * gc + e2, b, h);

        __threadfence();
        __syncthreads();
        if (tid == 0) atomicAdd(&g_flag[group], 1u);
        const unsigned target = 4u * (unsigned)(t + 1);
        while (ld_acq(&g_flag[group]) < target) {}

        // ---- import other slices' h, complete B tiles ----
#pragma unroll
        for (int d = 1; d < 4; d++) {
            int gp = (gc + d) & 3;
            float hv = __ldcg(&g_hx[p][group][gp][tid]);
            write_h(smem, 32 * gp + e2, b, hv);
        }
        __syncthreads();

#pragma unroll
        for (int c = 0; c < 4; c++) xpc[c] = xpn[c];
    }
}

// ---------------------------------------------------------------------------
extern "C" void kernel_launch(void* const* d_in, const int* in_sizes, int n_in,
                              void* d_out, int out_size)
{
    const float* x   = (const float*)d_in[0];
    const float* h0  = (const float*)d_in[1];
    const float* c0  = (const float*)d_in[2];
    const float* Wih = (const float*)d_in[3];
    const float* Whh = (const float*)d_in[4];
    const float* bih = (const float*)d_in[5];
    const float* bhh = (const float*)d_in[6];
    float* out = (float*)d_out;

    cudaFuncSetAttribute((const void*)xproj_gemm_pipe,
                         cudaFuncAttributeMaxDynamicSharedMemorySize, GEMM_SMEM);
    cudaFuncSetAttribute((const void*)lstm_rec_x,
                         cudaFuncAttributeMaxDynamicSharedMemorySize, REC_SMEM);

    void* flagPtr = nullptr;
    cudaGetSymbolAddress(&flagPtr, g_flag);
    cudaMemsetAsync(flagPtr, 0, 32 * sizeof(unsigned int));

    xproj_gemm_pipe<<<dim3(4, 2048), 256, GEMM_SMEM>>>(x, Wih, bih, bhh);
    lstm_rec_x<<<128, 256, REC_SMEM>>>(Whh, h0, c0, out);
}

// round 9
// speedup vs baseline: 1.4497x; 1.4497x over previous
#include <cuda_runtime.h>
#include <cuda_fp16.h>
#include <mma.h>
#include <math.h>
#include <stdint.h>

using namespace nvcuda;

#define T_STEPS 1024
#define BATCH   256
#define E_DIM   128

__device__ float g_xproj[134217728];

// ---------------------------------------------------------------------------
// helpers
// ---------------------------------------------------------------------------
__device__ __forceinline__ uint32_t smem_u32(const void* p) {
    uint32_t a;
    asm("{ .reg .u64 t; cvta.to.shared.u64 t, %1; cvt.u32.u64 %0, t; }" : "=r"(a) : "l"(p));
    return a;
}
__device__ __forceinline__ void cp16(uint32_t dst, const void* src) {
    asm volatile("cp.async.cg.shared.global [%0], [%1], 16;" :: "r"(dst), "l"(src));
}
__device__ __forceinline__ void cp_commit() { asm volatile("cp.async.commit_group;"); }
__device__ __forceinline__ void cp_wait0()  { asm volatile("cp.async.wait_group 0;"); }

#define GP 36   // smem pitch (floats)

// ---------------------------------------------------------------------------
// Kernel 1: x_proj = x @ W_ih^T + bias. tf32 wmma, cp.async double buffer,
// RN-rounding hoisted into one smem pass (no per-fragment converts).
// ---------------------------------------------------------------------------
__global__ __launch_bounds__(256, 2)
void xproj_gemm_pipe(const float* __restrict__ A,
                     const float* __restrict__ W,
                     const float* __restrict__ bih,
                     const float* __restrict__ bhh)
{
    extern __shared__ float sm[];
    float* Bsm   = sm + 2 * 128 * GP;
    float* BiasT = sm + 4 * 128 * GP;

    const int n0  = blockIdx.x * 128;
    const int m0  = blockIdx.y * 128;
    const int tid = threadIdx.x;
    const int warp = tid >> 5;
    const int wm = (warp >> 2) * 64;
    const int wn = (warp & 3) * 32;

    const uint32_t as_b = smem_u32(sm);
    const uint32_t bs_b = smem_u32(Bsm);
    const int lrow = tid >> 3;
    const int lkq  = (tid & 7) * 4;

    for (int i = tid; i < 16 * 128; i += 256) {
        int r = i >> 7, c = i & 127;
        BiasT[r * 132 + c] = bih[n0 + c] + bhh[n0 + c];
    }
    __syncthreads();

    wmma::fragment<wmma::accumulator, 16, 16, 8, float> cf[4][2];
#pragma unroll
    for (int i = 0; i < 4; i++)
#pragma unroll
        for (int j = 0; j < 2; j++)
            wmma::load_matrix_sync(cf[i][j], &BiasT[wn + j * 16], 132, wmma::mem_row_major);
    __syncthreads();

    auto issue = [&](int kt, int s) {
#pragma unroll
        for (int ld = 0; ld < 4; ld++) {
            int row = lrow + ld * 32;
            cp16(as_b + (uint32_t)(s * 128 * GP + row * GP + lkq) * 4,
                 &A[(size_t)(m0 + row) * 256 + kt * 32 + lkq]);
            cp16(bs_b + (uint32_t)(s * 128 * GP + row * GP + lkq) * 4,
                 &W[(size_t)(n0 + row) * 256 + kt * 32 + lkq]);
        }
        cp_commit();
    };

    issue(0, 0);
    for (int kt = 0; kt < 8; kt++) {
        int s = kt & 1;
        cp_wait0();
        // RN-round to tf32 in place (each thread rounds what it copied)
#pragma unroll
        for (int ld = 0; ld < 4; ld++) {
            int row = lrow + ld * 32;
            float* ap = &sm[s * 128 * GP + row * GP + lkq];
            float* bp = &Bsm[s * 128 * GP + row * GP + lkq];
#pragma unroll
            for (int q = 0; q < 4; q++) {
                ap[q] = wmma::__float_to_tf32(ap[q]);
                bp[q] = wmma::__float_to_tf32(bp[q]);
            }
        }
        __syncthreads();
        if (kt < 7) issue(kt + 1, s ^ 1);
        const float* As = sm + s * 128 * GP;
        const float* Bs = Bsm + s * 128 * GP;
#pragma unroll
        for (int kk = 0; kk < 32; kk += 8) {
            wmma::fragment<wmma::matrix_a, 16, 16, 8, wmma::precision::tf32, wmma::row_major> af[4];
            wmma::fragment<wmma::matrix_b, 16, 16, 8, wmma::precision::tf32, wmma::col_major> bf[2];
#pragma unroll
            for (int i = 0; i < 4; i++)
                wmma::load_matrix_sync(af[i], &As[(wm + i * 16) * GP + kk], GP);
#pragma unroll
            for (int j = 0; j < 2; j++)
                wmma::load_matrix_sync(bf[j], &Bs[(wn + j * 16) * GP + kk], GP);
#pragma unroll
            for (int i = 0; i < 4; i++)
#pragma unroll
                for (int j = 0; j < 2; j++)
                    wmma::mma_sync(cf[i][j], af[i], bf[j], cf[i][j]);
        }
        __syncthreads();
    }
#pragma unroll
    for (int i = 0; i < 4; i++)
#pragma unroll
        for (int j = 0; j < 2; j++)
            wmma::store_matrix_sync(
                &g_xproj[(size_t)(m0 + wm + i * 16) * 512 + n0 + wn + j * 16],
                cf[i][j], 512, wmma::mem_row_major);
}
#define GEMM_SMEM ((4 * 128 * GP + 16 * 132) * 4)

// ---------------------------------------------------------------------------
// Recurrence: fp16 mma.sync, hi/lo h-split packed into the n dimension.
// 64 CTAs x 4 batches, 256 threads. W_hh as ONE fp16 register copy.
// B tile [k=128][n=8]: cols 0-3 = h_hi(b0..3), cols 4-7 = h_lo(b0..3).
// One MMA sweep/step (32 mma/warp); hi+lo combined by shfl_xor butterfly.
// ---------------------------------------------------------------------------
__device__ __forceinline__ void mma16816h(float* c, const uint32_t* a, uint32_t b0, uint32_t b1) {
    asm volatile(
        "mma.sync.aligned.m16n8k16.row.col.f32.f16.f16.f32 "
        "{%0,%1,%2,%3}, {%4,%5,%6,%7}, {%8,%9}, {%0,%1,%2,%3};"
        : "+f"(c[0]), "+f"(c[1]), "+f"(c[2]), "+f"(c[3])
        : "r"(a[0]), "r"(a[1]), "r"(a[2]), "r"(a[3]), "r"(b0), "r"(b1));
}
__device__ __forceinline__ uint32_t pkhf(float x, float y) {
    __half2 h = __floats2half2_rn(x, y);
    return *reinterpret_cast<uint32_t*>(&h);
}
__device__ __forceinline__ float sigm(float x)   { return __fdividef(1.f, 1.f + __expf(-x)); }
__device__ __forceinline__ float tanhf_(float x) { float e = __expf(2.f * x); return 1.f - __fdividef(2.f, e + 1.f); }

// B-tile write: (k=e, col) -> byte
__device__ __forceinline__ void bt_write(char* bt, int e, int col, unsigned short v) {
    int kt = e >> 4, kk = e & 15;
    int half = kk >> 3, tq = (kk & 7) >> 1, lo2 = kk & 1;
    *reinterpret_cast<unsigned short*>(bt + kt * 256 + (col * 4 + tq) * 8 + half * 4 + lo2 * 2) = v;
}

__global__ __launch_bounds__(256, 1)
void lstm_rec_h4(const float* __restrict__ Whh,
                 const float* __restrict__ h0,
                 const float* __restrict__ c0,
                 float* __restrict__ out)
{
    __shared__ __align__(16) char Btile[2048];

    const int tid = threadIdx.x;
    const int w   = tid >> 5;
    const int l   = tid & 31;
    const int bg0 = blockIdx.x * 4;
    const int j   = l & 3;
    const int p   = j & 1;                  // batch pair
    const int cb  = (j < 2) ? 0 : 2;        // acc slot base for this thread
    const int e   = w * 16 + (l >> 2) + ((j < 2) ? 0 : 8);   // item hidden index

    // ---- W_hh fp16 A-fragments: [mt][kt][4] (row = mt*128 + w*16 + l>>2) ----
    uint32_t wf[4][8][4];
    {
        const int r0b = w * 16 + (l >> 2);
        const int t2  = 2 * (l & 3);
#pragma unroll
        for (int mt = 0; mt < 4; mt++)
#pragma unroll
            for (int kt = 0; kt < 8; kt++) {
                int r0 = mt * 128 + r0b;
                int k0 = kt * 16 + t2;
                const float* p00 = &Whh[(size_t)r0 * 128 + k0];
                const float* p10 = &Whh[(size_t)(r0 + 8) * 128 + k0];
                wf[mt][kt][0] = pkhf(p00[0], p00[1]);
                wf[mt][kt][1] = pkhf(p10[0], p10[1]);
                wf[mt][kt][2] = pkhf(p00[8], p00[9]);
                wf[mt][kt][3] = pkhf(p10[8], p10[9]);
            }
    }

    // ---- state + B-tile init: 2 items per thread: (e, b=2p), (e, b=2p+1) ----
    float creg[2];
#pragma unroll
    for (int i = 0; i < 2; i++) {
        int b = 2 * p + i;
        float h = h0[(size_t)(bg0 + b) * 128 + e];
        creg[i] = c0[(size_t)(bg0 + b) * 128 + e];
        __half hh = __float2half_rn(h);
        __half hl = __float2half_rn(h - __half2float(hh));
        bt_write(Btile, e, b,     __half_as_ushort(hh));
        bt_write(Btile, e, b + 4, __half_as_ushort(hl));
    }

    // xproj for step 0
    float xpc[4][2];
#pragma unroll
    for (int mt = 0; mt < 4; mt++)
#pragma unroll
        for (int i = 0; i < 2; i++)
            xpc[mt][i] = g_xproj[((size_t)bg0 + 2 * p + i) * 512 + mt * 128 + e];

    __syncthreads();

    for (int t = 0; t < T_STEPS; t++) {
        // prefetch next step xproj (hidden under MMA)
        float xpn[4][2];
        {
            int tn = (t + 1 < T_STEPS) ? t + 1 : t;
#pragma unroll
            for (int mt = 0; mt < 4; mt++)
#pragma unroll
                for (int i = 0; i < 2; i++)
                    xpn[mt][i] = __ldg(&g_xproj[((size_t)tn * BATCH + bg0 + 2 * p + i) * 512
                                                + mt * 128 + e]);
        }

        // ---- one MMA sweep ----
        float acc[4][4];
#pragma unroll
        for (int mt = 0; mt < 4; mt++)
#pragma unroll
            for (int c = 0; c < 4; c++) acc[mt][c] = 0.f;
#pragma unroll
        for (int kt = 0; kt < 8; kt++) {
            uint2 bv = *reinterpret_cast<const uint2*>(Btile + kt * 256 + l * 8);
#pragma unroll
            for (int mt = 0; mt < 4; mt++)
                mma16816h(acc[mt], wf[mt][kt], bv.x, bv.y);
        }
        __syncthreads();   // all warps done reading Btile

        // ---- butterfly: combine hi (cols 0-3) + lo (cols 4-7) partials ----
#pragma unroll
        for (int mt = 0; mt < 4; mt++)
#pragma unroll
            for (int c = 0; c < 4; c++)
                acc[mt][c] += __shfl_xor_sync(0xffffffffu, acc[mt][c], 2);

        // ---- epilogue: 2 items per thread ----
#pragma unroll
        for (int i = 0; i < 2; i++) {
            int c = cb + i;
            int b = 2 * p + i;
            float gi = acc[0][c] + xpc[0][i];
            float gf = acc[1][c] + xpc[1][i];
            float gg = acc[2][c] + xpc[2][i];
            float go = acc[3][c] + xpc[3][i];
            float i_ = sigm(gi), f_ = sigm(gf), g_ = tanhf_(gg), o_ = sigm(go);
            creg[i] = f_ * creg[i] + i_ * g_;
            float h = o_ * tanhf_(creg[i]);
            __half hh = __float2half_rn(h);
            __half hl = __float2half_rn(h - __half2float(hh));
            bt_write(Btile, e, b,     __half_as_ushort(hh));
            bt_write(Btile, e, b + 4, __half_as_ushort(hl));
            out[((size_t)t * BATCH + bg0 + b) * E_DIM + e] = log1pf(__expf(h));
        }
#pragma unroll
        for (int mt = 0; mt < 4; mt++)
#pragma unroll
            for (int i = 0; i < 2; i++) xpc[mt][i] = xpn[mt][i];
        __syncthreads();   // Btile ready for next step
    }
}

// ---------------------------------------------------------------------------
extern "C" void kernel_launch(void* const* d_in, const int* in_sizes, int n_in,
                              void* d_out, int out_size)
{
    const float* x   = (const float*)d_in[0];
    const float* h0  = (const float*)d_in[1];
    const float* c0  = (const float*)d_in[2];
    const float* Wih = (const float*)d_in[3];
    const float* Whh = (const float*)d_in[4];
    const float* bih = (const float*)d_in[5];
    const float* bhh = (const float*)d_in[6];
    float* out = (float*)d_out;

    cudaFuncSetAttribute((const void*)xproj_gemm_pipe,
                         cudaFuncAttributeMaxDynamicSharedMemorySize, GEMM_SMEM);

    xproj_gemm_pipe<<<dim3(4, 2048), 256, GEMM_SMEM>>>(x, Wih, bih, bhh);
    lstm_rec_h4<<<64, 256>>>(Whh, h0, c0, out);
}